// round 2
// baseline (speedup 1.0000x reference)
#include <cuda_runtime.h>

#define VOCAB 500
#define EMB   64
#define HID   64
#define BATCH 512
#define SEQ   512
#define NTOK  (BATCH * SEQ)

// Precomputed input projection: E'[v][i] = b_ih0[i] + sum_j emb[v][j]*W_ih0[i][j]
__device__ float g_xproj[VOCAB * HID];
// Converted (int64->int32 or passthrough) token indices, clamped to [0,VOCAB)
__device__ int g_idx[NTOK];

typedef unsigned long long u64;

__device__ __forceinline__ void fma2(u64 &d, u64 a, u64 b) {
    asm("fma.rn.f32x2 %0, %1, %2, %0;" : "+l"(d) : "l"(a), "l"(b));
}
__device__ __forceinline__ u64 add2(u64 a, u64 b) {
    u64 r; asm("add.rn.f32x2 %0, %1, %2;" : "=l"(r) : "l"(a), "l"(b)); return r;
}
__device__ __forceinline__ float2 unpack2(u64 v) {
    float2 r; asm("mov.b64 {%0,%1}, %2;" : "=f"(r.x), "=f"(r.y) : "l"(v)); return r;
}
__device__ __forceinline__ float fast_tanh(float x) {
    float e = __expf(2.0f * x);
    return 1.0f - __fdividef(2.0f, e + 1.0f);
}

// ---------------------------------------------------------------------------
// Kernel 0: detect index dtype (int64 vs int32) and convert to int32.
// Values are uniform in [0, 500): if the buffer is int64 (little-endian),
// every odd 32-bit word is 0. For int32 data the odds of 64 consecutive
// odd-position tokens all being 0 are (1/500)^64 ~ 0.
// ---------------------------------------------------------------------------
__global__ void convert_idx_kernel(const int* __restrict__ xw) {
    __shared__ int s_is64;
    if (threadIdx.x == 0) {
        int z = 0;
        #pragma unroll
        for (int k = 1; k < 128; k += 2) z |= xw[k];
        s_is64 = (z == 0);
    }
    __syncthreads();
    const int is64 = s_is64;
    int k = blockIdx.x * blockDim.x + threadIdx.x;
    if (k < NTOK) {
        int v = is64 ? xw[2 * k] : xw[k];
        v = min(max(v, 0), VOCAB - 1);   // safety clamp: never OOB
        g_idx[k] = v;
    }
}

// ---------------------------------------------------------------------------
// Kernel 1: fold embedding + layer-0 input projection into a 500x64 LUT.
// ---------------------------------------------------------------------------
__global__ void xproj_kernel(const float* __restrict__ emb,
                             const float* __restrict__ W_ih0,
                             const float* __restrict__ b_ih0) {
    __shared__ float se[EMB];
    const int v = blockIdx.x;
    const int i = threadIdx.x;
    se[i] = emb[v * EMB + i];
    __syncthreads();
    float acc = 0.0f;
    const float4* wr = (const float4*)(W_ih0 + i * EMB);
    #pragma unroll
    for (int q = 0; q < 16; q++) {
        float4 wv = __ldg(wr + q);
        acc += wv.x * se[4*q+0] + wv.y * se[4*q+1] + wv.z * se[4*q+2] + wv.w * se[4*q+3];
    }
    g_xproj[v * HID + i] = acc + b_ih0[i];
}

// ---------------------------------------------------------------------------
// Kernel 2: per-row sequential scan. One CTA (64 threads, 2 warps) per batch
// row. Warp w owns j in [32w, 32w+32); lane L owns outputs i0=L, i1=L+32.
// Weights held in registers as f32x2 pairs along j; h broadcast from smem.
// ---------------------------------------------------------------------------
__global__ void __launch_bounds__(64)
scan_kernel(const float* __restrict__ W_hh0,
            const float* __restrict__ b_hh0,
            const float* __restrict__ W_ih1,
            const float* __restrict__ W_hh1,
            const float* __restrict__ b_ih1,
            const float* __restrict__ b_hh1,
            const float* __restrict__ fc_w,
            const float* __restrict__ fc_b,
            float* __restrict__ out) {
    __shared__ __align__(16) float sh1[HID];
    __shared__ __align__(16) float sh2[HID];
    __shared__ float2 spart[2][32];
    __shared__ float  sx[2][HID];
    __shared__ int    sidx[SEQ];

    const int tid  = threadIdx.x;
    const int w    = tid >> 5;
    const int lane = tid & 31;
    const int b    = blockIdx.x;
    const int i0   = lane;
    const int i1   = lane + 32;
    const int jbase = w * 32;

    // --- load weight rows into registers as (W[i][2q], W[i][2q+1]) pairs ---
    u64 whh0_a[16], whh0_b[16], wih1_a[16], wih1_b[16], whh1_a[16], whh1_b[16];
    {
        const u64* p0 = (const u64*)(W_hh0 + i0 * HID + jbase);
        const u64* p1 = (const u64*)(W_hh0 + i1 * HID + jbase);
        const u64* p2 = (const u64*)(W_ih1 + i0 * HID + jbase);
        const u64* p3 = (const u64*)(W_ih1 + i1 * HID + jbase);
        const u64* p4 = (const u64*)(W_hh1 + i0 * HID + jbase);
        const u64* p5 = (const u64*)(W_hh1 + i1 * HID + jbase);
        #pragma unroll
        for (int q = 0; q < 16; q++) {
            whh0_a[q] = __ldg(p0 + q);
            whh0_b[q] = __ldg(p1 + q);
            wih1_a[q] = __ldg(p2 + q);
            wih1_b[q] = __ldg(p3 + q);
            whh1_a[q] = __ldg(p4 + q);
            whh1_b[q] = __ldg(p5 + q);
        }
    }
    const float bias1_0 = b_hh0[i0];
    const float bias1_1 = b_hh0[i1];
    const float bias2_0 = b_ih1[i0] + b_hh1[i0];
    const float bias2_1 = b_ih1[i1] + b_hh1[i1];

    // --- stage indices into smem, zero-init hidden states ---
    const int* xr = g_idx + b * SEQ;
    #pragma unroll
    for (int k = tid; k < SEQ; k += 64) sidx[k] = xr[k];
    sh1[tid] = 0.0f;
    sh2[tid] = 0.0f;
    __syncthreads();

    // prefetch step-0 input row
    sx[0][tid] = g_xproj[sidx[0] * HID + tid];

    const u64* ph1 = (const u64*)(sh1 + jbase);
    const u64* ph2 = (const u64*)(sh2 + jbase);

    float h2n0 = 0.0f, h2n1 = 0.0f;

    for (int t = 0; t < SEQ; t++) {
        const int cur = t & 1, nxt = cur ^ 1;

        // prefetch next step's input row (LDG issued early, hidden by matvecs)
        float xnext = 0.0f;
        const bool has_next = (t + 1 < SEQ);
        if (has_next) xnext = __ldg(&g_xproj[sidx[t + 1] * HID + tid]);

        // --- stage A: p1 = Whh0*h1 (own j range), p2 = Whh1*h2 (independent) ---
        u64 a0 = 0, a1 = 0, a2 = 0, a3 = 0;   // p1 for i0 (2 chains), i1 (2 chains)
        u64 c0 = 0, c1 = 0, c2 = 0, c3 = 0;   // p2
        #pragma unroll
        for (int q = 0; q < 16; q += 2) {
            u64 h1p = ph1[q], h1q = ph1[q + 1];
            fma2(a0, whh0_a[q], h1p); fma2(a1, whh0_a[q + 1], h1q);
            fma2(a2, whh0_b[q], h1p); fma2(a3, whh0_b[q + 1], h1q);
            u64 h2p = ph2[q], h2q = ph2[q + 1];
            fma2(c0, whh1_a[q], h2p); fma2(c1, whh1_a[q + 1], h2q);
            fma2(c2, whh1_b[q], h2p); fma2(c3, whh1_b[q + 1], h2q);
        }
        float2 pa = unpack2(add2(a0, a1));
        float2 pb = unpack2(add2(a2, a3));
        const float p1_0 = pa.x + pa.y;
        const float p1_1 = pb.x + pb.y;
        spart[w][lane] = make_float2(p1_0, p1_1);
        if (has_next) sx[nxt][tid] = xnext;
        __syncthreads();  // S1: p1 partials exchanged

        float2 po = spart[w ^ 1][lane];
        const float h1n0 = fast_tanh(p1_0 + po.x + sx[cur][i0] + bias1_0);
        const float h1n1 = fast_tanh(p1_1 + po.y + sx[cur][i1] + bias1_1);
        if (w == 0) { sh1[i0] = h1n0; sh1[i1] = h1n1; }
        __syncthreads();  // S2: h1 updated

        // --- stage B: p3 = Wih1*h1new, accumulated on top of p2 ---
        #pragma unroll
        for (int q = 0; q < 16; q += 2) {
            u64 hp = ph1[q], hq = ph1[q + 1];
            fma2(c0, wih1_a[q], hp); fma2(c1, wih1_a[q + 1], hq);
            fma2(c2, wih1_b[q], hp); fma2(c3, wih1_b[q + 1], hq);
        }
        float2 qa = unpack2(add2(c0, c1));
        float2 qb = unpack2(add2(c2, c3));
        const float p23_0 = qa.x + qa.y;
        const float p23_1 = qb.x + qb.y;
        spart[w][lane] = make_float2(p23_0, p23_1);
        __syncthreads();  // S3: p2+p3 partials exchanged

        float2 qo = spart[w ^ 1][lane];
        h2n0 = fast_tanh(p23_0 + qo.x + bias2_0);
        h2n1 = fast_tanh(p23_1 + qo.y + bias2_1);
        if (w == 0) { sh2[i0] = h2n0; sh2[i1] = h2n1; }
        __syncthreads();  // S4: h2 updated
    }

    // --- final projection: out[b] = fc_w . h2 + fc_b (warp 0 only) ---
    if (w == 0) {
        float partial = fc_w[i0] * h2n0 + fc_w[i1] * h2n1;
        #pragma unroll
        for (int off = 16; off; off >>= 1)
            partial += __shfl_xor_sync(0xffffffffu, partial, off);
        if (lane == 0) out[b] = partial + fc_b[0];
    }
}

// ---------------------------------------------------------------------------
extern "C" void kernel_launch(void* const* d_in, const int* in_sizes, int n_in,
                              void* d_out, int out_size) {
    const int*   x_raw = (const int*)d_in[0];     // int32 view; dtype detected on device
    const float* emb   = (const float*)d_in[1];
    const float* W_ih0 = (const float*)d_in[2];
    const float* W_hh0 = (const float*)d_in[3];
    const float* b_ih0 = (const float*)d_in[4];
    const float* b_hh0 = (const float*)d_in[5];
    const float* W_ih1 = (const float*)d_in[6];
    const float* W_hh1 = (const float*)d_in[7];
    const float* b_ih1 = (const float*)d_in[8];
    const float* b_hh1 = (const float*)d_in[9];
    const float* fc_w  = (const float*)d_in[10];
    const float* fc_b  = (const float*)d_in[11];
    float*       out   = (float*)d_out;

    convert_idx_kernel<<<(NTOK + 255) / 256, 256>>>(x_raw);
    xproj_kernel<<<VOCAB, HID>>>(emb, W_ih0, b_ih0);
    scan_kernel<<<BATCH, 64>>>(W_hh0, b_hh0, W_ih1, W_hh1, b_ih1, b_hh1,
                               fc_w, fc_b, out);
}